// round 5
// baseline (speedup 1.0000x reference)
#include <cuda_runtime.h>
#include <cuda_fp16.h>
#include <cstdint>

// ============================================================================
// Problem dims (fixed by setup_inputs)
// ============================================================================
#define DIN    2048
#define DOUT   2048
#define MROWS  8192        // B*S = 4*2048
#define GROUPS 64          // DIN/32

// ============================================================================
// Scratch (device globals; no allocation allowed)
// ============================================================================
__device__ __half g_xq[(size_t)MROWS * DIN];   // quantized x as exact integers in fp16
__device__ __half g_wh[(size_t)DOUT * DIN];    // dequantized weights in fp16
__device__ float  g_xscale[MROWS];             // per-token scale

// ============================================================================
// Portable PTX helpers (sm_80-level only: cp.async, ldmatrix, mma.sync)
// ============================================================================
__device__ __forceinline__ uint32_t smem_to_u32(const void* smem_ptr) {
    uint32_t addr;
    asm("{ .reg .u64 tmp; cvta.to.shared.u64 tmp, %1; cvt.u32.u64 %0, tmp; }"
        : "=r"(addr) : "l"(smem_ptr));
    return addr;
}

__device__ __forceinline__ void cp_async16(uint32_t smem_addr, const void* gptr) {
    asm volatile("cp.async.cg.shared.global [%0], [%1], 16;"
                 :: "r"(smem_addr), "l"(gptr));
}

__device__ __forceinline__ void ldsm_x4(uint32_t* r, uint32_t addr) {
    asm volatile("ldmatrix.sync.aligned.m8n8.x4.shared.b16 {%0,%1,%2,%3}, [%4];"
                 : "=r"(r[0]), "=r"(r[1]), "=r"(r[2]), "=r"(r[3])
                 : "r"(addr));
}

__device__ __forceinline__ void mma16816(float* d, const uint32_t* a,
                                         uint32_t b0, uint32_t b1) {
    asm volatile(
        "mma.sync.aligned.m16n8k16.row.col.f32.f16.f16.f32 "
        "{%0,%1,%2,%3}, {%4,%5,%6,%7}, {%8,%9}, {%0,%1,%2,%3};"
        : "+f"(d[0]), "+f"(d[1]), "+f"(d[2]), "+f"(d[3])
        : "r"(a[0]), "r"(a[1]), "r"(a[2]), "r"(a[3]), "r"(b0), "r"(b1));
}

// ============================================================================
// Kernel 1: per-token asymmetric int8 fake-quant of x (exact jnp replication)
// Writes qx = (q - zp) as exact fp16 integers, plus per-row scale.
// ============================================================================
__device__ __forceinline__ float qdq_elem(float xv, float scale, float zpf) {
    float q = rintf(__fdiv_rn(xv, scale)) + zpf;   // round-half-even like jnp.round
    q = fminf(fmaxf(q, -128.0f), 127.0f);
    return q - zpf;   // integer in [-255, 255], exact in fp16
}

__global__ void __launch_bounds__(256)
quant_x_kernel(const float* __restrict__ x) {
    __shared__ float red[18];
    const int row = blockIdx.x;
    const int tid = threadIdx.x;
    const float4* xr = (const float4*)(x + (size_t)row * DIN);
    float4 v0 = xr[tid];
    float4 v1 = xr[tid + 256];

    float mn = 0.0f, mx = 0.0f;   // reference min/max include 0
    mn = fminf(mn, fminf(fminf(v0.x, v0.y), fminf(v0.z, v0.w)));
    mn = fminf(mn, fminf(fminf(v1.x, v1.y), fminf(v1.z, v1.w)));
    mx = fmaxf(mx, fmaxf(fmaxf(v0.x, v0.y), fmaxf(v0.z, v0.w)));
    mx = fmaxf(mx, fmaxf(fmaxf(v1.x, v1.y), fmaxf(v1.z, v1.w)));

    #pragma unroll
    for (int off = 16; off > 0; off >>= 1) {
        mn = fminf(mn, __shfl_xor_sync(0xffffffffu, mn, off));
        mx = fmaxf(mx, __shfl_xor_sync(0xffffffffu, mx, off));
    }
    if ((tid & 31) == 0) { red[tid >> 5] = mn; red[8 + (tid >> 5)] = mx; }
    __syncthreads();
    if (tid == 0) {
        float m1 = red[0], m2 = red[8];
        #pragma unroll
        for (int w = 1; w < 8; w++) {
            m1 = fminf(m1, red[w]);
            m2 = fmaxf(m2, red[8 + w]);
        }
        float scale = fmaxf(__fdiv_rn(m2 - m1, 255.0f), 1.1920929e-07f);
        float zpf = -128.0f - rintf(__fdiv_rn(m1, scale));
        zpf = fminf(fmaxf(zpf, -128.0f), 127.0f);
        red[16] = scale;
        red[17] = zpf;
        g_xscale[row] = scale;
    }
    __syncthreads();
    const float scale = red[16];
    const float zpf   = red[17];

    __half2* xq2 = (__half2*)(g_xq + (size_t)row * DIN);
    xq2[2 * tid]             = __floats2half2_rn(qdq_elem(v0.x, scale, zpf), qdq_elem(v0.y, scale, zpf));
    xq2[2 * tid + 1]         = __floats2half2_rn(qdq_elem(v0.z, scale, zpf), qdq_elem(v0.w, scale, zpf));
    xq2[2 * (tid + 256)]     = __floats2half2_rn(qdq_elem(v1.x, scale, zpf), qdq_elem(v1.y, scale, zpf));
    xq2[2 * (tid + 256) + 1] = __floats2half2_rn(qdq_elem(v1.z, scale, zpf), qdq_elem(v1.w, scale, zpf));
}

// ============================================================================
// Kernel 2: grouped-int4 dequant of W into fp16
// ============================================================================
__global__ void __launch_bounds__(256)
dequant_w_kernel(const int* __restrict__ wi,
                 const float* __restrict__ ws,
                 const float* __restrict__ wz) {
    const int idx = blockIdx.x * 256 + threadIdx.x;   // one int4 vec (4 elements)
    const int4 w4 = ((const int4*)wi)[idx];
    const int base = idx << 2;
    const int o = base >> 11;                 // / DIN
    const int g = (base & (DIN - 1)) >> 5;    // group of 32
    const float s = ws[o * GROUPS + g];
    const float z = wz[o * GROUPS + g];
    __half2 h01 = __floats2half2_rn(((float)w4.x - z) * s, ((float)w4.y - z) * s);
    __half2 h23 = __floats2half2_rn(((float)w4.z - z) * s, ((float)w4.w - z) * s);
    __half2* dst = (__half2*)(g_wh + base);
    dst[0] = h01;
    dst[1] = h23;
}

// ============================================================================
// Kernel 3: fp16 mma.sync GEMM (NT), 128x128x64 tiles, cp.async double buffer
//   out[m, n] = g_xscale[m] * sum_k g_xq[m,k] * g_wh[n,k]
//
// SMEM layout: padded rows, 64 fp16 data + 8 fp16 pad = 144B stride.
//   - ldmatrix 8-row access: rows 144B apart -> 4-bank stride -> conflict-free
//   - cp.async 16B chunks: 8 per row, aligned
// ============================================================================
static constexpr int BM = 128;
static constexpr int BN = 128;
static constexpr int BK = 64;
static constexpr int KITERS = DIN / BK;           // 32
static constexpr int SSTRIDE = 72;                // halves per smem row (64 + 8 pad)
static constexpr int SROWB = SSTRIDE * 2;         // 144 bytes per row
static constexpr int TILE_H = 128 * SSTRIDE;      // halves per tile (9216)
static constexpr int STAGE_H = 2 * TILE_H;        // A + B per stage
static constexpr int GEMM_SMEM = 2 * STAGE_H * 2; // 2 stages, bytes = 73728

__global__ void __launch_bounds__(256, 2)
qgemm_kernel(float* __restrict__ out) {
    extern __shared__ __half sm[];
    const uint32_t sbase = smem_to_u32(sm);
    const int tid  = threadIdx.x;
    const int lane = tid & 31;
    const int wid  = tid >> 5;
    const int warp_m = wid & 3;    // 4 m-tiles of 32 rows
    const int warp_n = wid >> 2;   // 2 n-tiles of 64 cols
    const int n0 = blockIdx.x * BN;
    const int m0 = blockIdx.y * BM;

    const __half* ga = g_xq + (size_t)m0 * DIN;
    const __half* gb = g_wh + (size_t)n0 * DIN;

    auto load_stage = [&](int s, int k0) {
        const uint32_t abase = sbase + (uint32_t)(s * STAGE_H) * 2;
        const uint32_t bbase = abase + (uint32_t)TILE_H * 2;
        #pragma unroll
        for (int it = 0; it < 4; it++) {
            int c = tid + it * 256;          // 0..1023, one 16B chunk each
            int r = c >> 3;                  // row 0..127
            int colh = (c & 7) * 8;          // column in halves (0..56)
            uint32_t soff = (uint32_t)(r * SROWB + colh * 2);
            cp_async16(abase + soff, ga + (size_t)r * DIN + k0 + colh);
            cp_async16(bbase + soff, gb + (size_t)r * DIN + k0 + colh);
        }
        asm volatile("cp.async.commit_group;" ::: "memory");
    };

    float acc[2][8][4];
    #pragma unroll
    for (int mi = 0; mi < 2; mi++)
        #pragma unroll
        for (int ni = 0; ni < 8; ni++)
            #pragma unroll
            for (int j = 0; j < 4; j++)
                acc[mi][ni][j] = 0.0f;

    load_stage(0, 0);

    const uint32_t a_row = (uint32_t)(warp_m * 32 + (lane & 15));
    const uint32_t b_row = (uint32_t)(warp_n * 64 + (lane & 15));
    const uint32_t khalf = (uint32_t)((lane >> 4) * 8);

    for (int i = 0; i < KITERS; i++) {
        asm volatile("cp.async.wait_group 0;" ::: "memory");
        __syncthreads();
        if (i + 1 < KITERS) load_stage((i + 1) & 1, (i + 1) * BK);

        const uint32_t abase = sbase + (uint32_t)((i & 1) * STAGE_H) * 2;
        const uint32_t bbase = abase + (uint32_t)TILE_H * 2;

        #pragma unroll
        for (int ka = 0; ka < 4; ka++) {
            const uint32_t kof = (uint32_t)(ka * 16 + khalf) * 2;   // bytes
            uint32_t a[2][4];
            uint32_t b[4][4];
            ldsm_x4(a[0], abase + a_row * SROWB + kof);
            ldsm_x4(a[1], abase + (a_row + 16) * SROWB + kof);
            #pragma unroll
            for (int p = 0; p < 4; p++)
                ldsm_x4(b[p], bbase + (b_row + p * 16) * SROWB + kof);

            #pragma unroll
            for (int mi = 0; mi < 2; mi++) {
                #pragma unroll
                for (int p = 0; p < 4; p++) {
                    // x4 B load covers n-atoms 2p (regs 0,2) and 2p+1 (regs 1,3)
                    mma16816(acc[mi][2 * p],     a[mi], b[p][0], b[p][2]);
                    mma16816(acc[mi][2 * p + 1], a[mi], b[p][1], b[p][3]);
                }
            }
        }
        __syncthreads();   // protect stage (i&1) from iter i+1's refill
    }

    // Epilogue: scale by per-token scale, store fp32.
    const int qrow = lane >> 2;          // 0..7
    const int qcol = (lane & 3) * 2;     // 0,2,4,6
    #pragma unroll
    for (int mi = 0; mi < 2; mi++) {
        const int mrow0 = m0 + warp_m * 32 + mi * 16 + qrow;
        const float sc0 = g_xscale[mrow0];
        const float sc1 = g_xscale[mrow0 + 8];
        float* o0 = out + (size_t)mrow0 * DOUT + n0 + warp_n * 64 + qcol;
        float* o1 = o0 + (size_t)8 * DOUT;
        #pragma unroll
        for (int ni = 0; ni < 8; ni++) {
            *(float2*)(o0 + ni * 8) = make_float2(sc0 * acc[mi][ni][0],
                                                  sc0 * acc[mi][ni][1]);
            *(float2*)(o1 + ni * 8) = make_float2(sc1 * acc[mi][ni][2],
                                                  sc1 * acc[mi][ni][3]);
        }
    }
}

// ============================================================================
// Launch
// ============================================================================
extern "C" void kernel_launch(void* const* d_in, const int* in_sizes, int n_in,
                              void* d_out, int out_size) {
    (void)in_sizes; (void)n_in; (void)out_size;
    const float* x  = (const float*)d_in[0];
    const int*   wi = (const int*)d_in[1];
    const float* ws = (const float*)d_in[2];
    const float* wz = (const float*)d_in[3];
    float* out = (float*)d_out;

    cudaFuncSetAttribute(qgemm_kernel,
                         cudaFuncAttributeMaxDynamicSharedMemorySize, GEMM_SMEM);

    quant_x_kernel<<<MROWS, 256>>>(x);
    dequant_w_kernel<<<(DOUT * DIN) / 1024, 256>>>(wi, ws, wz);
    qgemm_kernel<<<dim3(DOUT / BN, MROWS / BM), 256, GEMM_SMEM>>>(out);
}